// round 15
// baseline (speedup 1.0000x reference)
#include <cuda_runtime.h>
#include <cuda_bf16.h>

#define D_MODEL     4096
#define SHARDS      8
#define TOK_PER_BLK 32            // grid = 4*128 = 512 -> SINGLE balanced wave
#define BATCH       8             // loads in flight per thread before stores
#define THREADS     256           // each thread owns one float4 -> chunk = 1024 floats
#define N_CHUNKS    (D_MODEL / (THREADS * 4))   // 4

// Fused: out[t, :] = W[x[t], :] + sum_s b[s, :].
// Block = (column chunk of 1024 floats) x (group of 32 tokens).
//
// Round-10 ncu showed 1024 blocks / (5 resident x 148 SM) = 1.38 waves: a
// ~38%-full tail wave ran at a fraction of chip BW, pinning DRAM at 46%.
// 512 blocks at 48 regs (5 blocks/SM capacity = 740) is ONE balanced wave:
// every block does identical work (4 batches of 8 tokens), no tail.
__global__ void __launch_bounds__(THREADS) fused_gather_kernel(
    const int* __restrict__ x32,
    const float* __restrict__ W,
    const float* __restrict__ b,
    float* __restrict__ out,
    int n_tok)
{
    const int pos = blockIdx.x * (THREADS * 4) + threadIdx.x * 4;  // d-index
    const int t0  = blockIdx.y * TOK_PER_BLK;

    // Per-thread bias sum (one float4) across 8 shards (b is 128 KB, L2-hot).
    float4 bias = make_float4(0.f, 0.f, 0.f, 0.f);
    #pragma unroll
    for (int s = 0; s < SHARDS; s++) {
        const float4 v = __ldg((const float4*)(b + s * D_MODEL + pos));
        bias.x += v.x; bias.y += v.y; bias.z += v.z; bias.w += v.w;
    }

    // Token-dtype detect (int64 buffers have zero high words at odd int32
    // indices; P(false positive for int32) ~ (1/50400)^4). L1/L2-resident.
    const bool is64 = (x32[1] | x32[3] | x32[5] | x32[7]) == 0;

    // Stage this group's 32 token ids in shared memory.
    // Out-of-range tokens clamp to 0 (row 0 is a valid load; store is
    // predicated off below).
    __shared__ long long toks[TOK_PER_BLK];
    if (threadIdx.x < TOK_PER_BLK) {
        const int t = t0 + threadIdx.x;
        long long tk = 0;
        if (t < n_tok)
            tk = is64 ? ((const long long*)x32)[t] : (long long)x32[t];
        toks[threadIdx.x] = tk;
    }
    __syncthreads();

    #pragma unroll
    for (int i0 = 0; i0 < TOK_PER_BLK; i0 += BATCH) {
        float4 w[BATCH];
        // Phase 1: batch all loads (independent -> issued back-to-back, MLP=8).
        #pragma unroll
        for (int k = 0; k < BATCH; k++) {
            w[k] = __ldcs((const float4*)(W + toks[i0 + k] * (long long)D_MODEL + pos));
        }
        // Phase 2: add bias + predicated streaming stores.
        #pragma unroll
        for (int k = 0; k < BATCH; k++) {
            const int t = t0 + i0 + k;
            float4 r;
            r.x = w[k].x + bias.x; r.y = w[k].y + bias.y;
            r.z = w[k].z + bias.z; r.w = w[k].w + bias.w;
            if (t < n_tok)
                __stcs((float4*)(out + (long long)t * D_MODEL + pos), r);
        }
    }
}

extern "C" void kernel_launch(void* const* d_in, const int* in_sizes, int n_in,
                              void* d_out, int out_size) {
    // Bind inputs by element count (robust to metadata ordering):
    //   x: 4096 tokens (int32 or int64), b: 8*4096 = 32768 fp32,
    //   W: 50400*4096 fp32 (the big one).
    const void*  x = nullptr;
    const float* W = nullptr;
    const float* b = nullptr;
    int n_tok = 4096;

    long long w_sz = -1;
    int w_idx = -1;
    for (int i = 0; i < n_in; i++) {
        if ((long long)in_sizes[i] > w_sz) { w_sz = in_sizes[i]; w_idx = i; }
    }
    W = (const float*)d_in[w_idx];
    for (int i = 0; i < n_in; i++) {
        if (i == w_idx) continue;
        if (in_sizes[i] == SHARDS * D_MODEL) b = (const float*)d_in[i];
        else { x = d_in[i]; n_tok = in_sizes[i]; }
    }

    float* out = (float*)d_out;

    dim3 grid(N_CHUNKS, (n_tok + TOK_PER_BLK - 1) / TOK_PER_BLK);
    fused_gather_kernel<<<grid, THREADS>>>((const int*)x, W, b, out, n_tok);
}